// round 9
// baseline (speedup 1.0000x reference)
#include <cuda_runtime.h>
#include <math.h>
#include <stdint.h>

// ---------------------------------------------------------------------------
// Problem constants
// ---------------------------------------------------------------------------
#define BATCH 8192
#define DIN   4096
#define DMODEL 512
#define DFF   2048
#define NHEAD 3
#define HDIM  256
#define OUTD  896

// ---------------------------------------------------------------------------
// HMMA tf32 GEMM tiling: 128x128x32, 512 threads, warp tile 32x32
// ---------------------------------------------------------------------------
#define BM 128
#define BN 128
#define BK 32
#define NSTAGE 4
#define NTH 512
#define TILE_F 4096           // floats per operand tile (128*32)
#define STAGE_F (2*TILE_F)
#define SMEM_BYTES (NSTAGE * STAGE_F * 4)   // 131072

// ---------------------------------------------------------------------------
// Scratch (device globals; no allocation allowed)
// ---------------------------------------------------------------------------
__device__ float g_xr [BATCH * DIN];      // rounded + k-permuted copy of x
__device__ float g_h0 [BATCH * DMODEL];
__device__ float g_h0r[BATCH * DMODEL];   // permuted+rounded copy of h0
__device__ float g_h  [BATCH * DMODEL];
__device__ float g_lnb[BATCH * DMODEL];   // permuted
__device__ float g_t  [BATCH * DMODEL];   // permuted
__device__ float g_ff [BATCH * DFF];      // permuted
__device__ float g_z  [BATCH * NHEAD * HDIM];
__device__ float g_z2 [BATCH * NHEAD * HDIM];  // permuted

// transposed + tf32-rounded + k-permuted weights [N,K]
#define OFF_WIN  0
#define OFF_WVSA 2097152
#define OFF_WOSA 2359296
#define OFF_WVCA 2621440
#define OFF_WOCA 2883584
#define OFF_FF1  3145728
#define OFF_FF2  4194304
#define OFF_WH1  5242880
#define OFF_WH2  5636096
#define WT_TOTAL 6324224
__device__ float g_wt[WT_TOTAL];

// ---------------------------------------------------------------------------
// Helpers
// ---------------------------------------------------------------------------
__device__ __forceinline__ float tf32r(float f) {
    unsigned u;
    asm("cvt.rna.tf32.f32 %0, %1;" : "=r"(u) : "f"(f));
    return __uint_as_float(u);
}
__device__ __forceinline__ unsigned f2u(float f) { return __float_as_uint(f); }

__device__ __forceinline__ float gelu_exact(float v) {
    return 0.5f * v * (1.0f + erff(v * 0.7071067811865476f));
}

// permuted position of column/k index c within its 32-block:
// p = (c%4)*8 + ((c%32)/8)*2 + ((c/4)%2)
__device__ __forceinline__ int permcol(int c) {
    return (c & ~31) + ((c & 3) * 8 + ((c & 31) >> 3) * 2 + ((c >> 2) & 1));
}
// inverse within a 32-block: source index for permuted position p
__device__ __forceinline__ int invperm(int p) {
    return (p >> 3) + (((p >> 1) & 3) << 3) + ((p & 1) << 2);
}

__device__ __forceinline__ uint32_t smem_u32(const void* p) {
    uint32_t a;
    asm("{ .reg .u64 t; cvta.to.shared.u64 t, %1; cvt.u32.u64 %0, t; }" : "=r"(a) : "l"(p));
    return a;
}
__device__ __forceinline__ void cp16(uint32_t s, const void* g) {
    asm volatile("cp.async.cg.shared.global [%0], [%1], 16;" :: "r"(s), "l"(g) : "memory");
}

#define MMA(d, a0,a1,a2,a3, b0,b1) \
    asm volatile("mma.sync.aligned.m16n8k8.row.col.f32.tf32.tf32.f32 " \
        "{%0,%1,%2,%3},{%4,%5,%6,%7},{%8,%9},{%0,%1,%2,%3};" \
        : "+f"((d)[0]), "+f"((d)[1]), "+f"((d)[2]), "+f"((d)[3]) \
        : "r"(a0), "r"(a1), "r"(a2), "r"(a3), "r"(b0), "r"(b1))

// ---------------------------------------------------------------------------
// tf32 GEMM via mma.sync: C[M,N] = A[M,K] @ Bt[N,K]^T
// A and Bt both tf32-rounded and k-permuted within 32-blocks.
// Epilogue: +bias(+z-stride) +bias2 +resid, optional gelu / tf32 round,
// output plain or permuted, optional second permuted+rounded copy Cr.
// ---------------------------------------------------------------------------
__global__ void __launch_bounds__(NTH, 1)
gemm_mma(const float* __restrict__ A, int lda, int az,
         const float* __restrict__ Bt, int K, int bz,
         float* __restrict__ C, int ldc, int cz,
         float* __restrict__ Cr,
         const float* __restrict__ bias, int biasz,
         const float* __restrict__ bias2,
         const float* __restrict__ resid, int ldres,
         int dogelu, int doround, int permC)
{
    extern __shared__ float smemf[];
    const uint32_t sb = smem_u32(smemf);

    A  += (size_t)blockIdx.z * az;
    Bt += (size_t)blockIdx.z * bz;
    C  += (size_t)blockIdx.z * cz;
    if (bias) bias += (size_t)blockIdx.z * biasz;

    const int tid = threadIdx.x;
    const int wid = tid >> 5, lane = tid & 31;
    const int g = lane >> 2, tg = lane & 3;
    const int wm = wid & 3, wn = wid >> 2;        // 4x4 warp grid
    const int tile_m = blockIdx.y * BM;
    const int tile_n = blockIdx.x * BN;
    const int ktiles = K / BK;

    // loader indices: each thread one row (lr) and one quarter (lj)
    const int lr = tid >> 2;                      // 0..127
    const int lj = tid & 3;                       // 0..3
    const int lsw = lr & 7;

    float acc[2][4][4];
    #pragma unroll
    for (int i = 0; i < 2; i++)
        #pragma unroll
        for (int j = 0; j < 4; j++)
            #pragma unroll
            for (int r = 0; r < 4; r++) acc[i][j][r] = 0.f;

    auto load_stage = [&](int buf, int k0) {
        uint32_t da = sb + (buf * STAGE_F + lr * 32) * 4;
        const float* sa = A + (size_t)(tile_m + lr) * lda + k0;
        cp16(da + ((lj)     ^ lsw) * 16, sa + lj * 4);
        cp16(da + ((lj + 4) ^ lsw) * 16, sa + (lj + 4) * 4);
        uint32_t db = sb + (buf * STAGE_F + TILE_F + lr * 32) * 4;
        const float* sbp = Bt + (size_t)(tile_n + lr) * K + k0;
        cp16(db + ((lj)     ^ lsw) * 16, sbp + lj * 4);
        cp16(db + ((lj + 4) ^ lsw) * 16, sbp + (lj + 4) * 4);
    };

    // ---- prologue: stages 0, 1 ----
    load_stage(0, 0);
    asm volatile("cp.async.commit_group;" ::: "memory");
    load_stage(1, BK);
    asm volatile("cp.async.commit_group;" ::: "memory");

    // ---- main loop ----
    for (int kt = 0; kt < ktiles; kt++) {
        asm volatile("cp.async.wait_group 1;" ::: "memory");
        __syncthreads();

        const float* as = smemf + (kt % NSTAGE) * STAGE_F;
        const float* bs = as + TILE_F;

        // load ALL fragments for this ktile (16 LDS.128) before any MMA
        float4 af[2][2][2], bf[2][4];
        #pragma unroll
        for (int j2 = 0; j2 < 2; j2++) {
            const int gsw = ((2 * tg + j2) ^ g) * 4;
            #pragma unroll
            for (int mi = 0; mi < 2; mi++) {
                const int r0 = wm * 32 + mi * 16 + g;
                af[j2][mi][0] = *(const float4*)(as + r0 * 32 + gsw);
                af[j2][mi][1] = *(const float4*)(as + (r0 + 8) * 32 + gsw);
            }
            #pragma unroll
            for (int ni = 0; ni < 4; ni++) {
                const int n0 = wn * 32 + ni * 8 + g;
                bf[j2][ni] = *(const float4*)(bs + n0 * 32 + gsw);
            }
        }

        // prefetch stage kt+2 NOW — a full ktile of MMAs covers its latency
        const int pf = kt + 2;
        if (pf < ktiles) load_stage(pf % NSTAGE, pf * BK);
        asm volatile("cp.async.commit_group;" ::: "memory");

        #pragma unroll
        for (int j2 = 0; j2 < 2; j2++)
            #pragma unroll
            for (int ni = 0; ni < 4; ni++)
                #pragma unroll
                for (int mi = 0; mi < 2; mi++) {
                    MMA(acc[mi][ni],
                        f2u(af[j2][mi][0].x), f2u(af[j2][mi][1].x),
                        f2u(af[j2][mi][0].y), f2u(af[j2][mi][1].y),
                        f2u(bf[j2][ni].x), f2u(bf[j2][ni].y));
                    MMA(acc[mi][ni],
                        f2u(af[j2][mi][0].z), f2u(af[j2][mi][1].z),
                        f2u(af[j2][mi][0].w), f2u(af[j2][mi][1].w),
                        f2u(bf[j2][ni].z), f2u(bf[j2][ni].w));
                }
    }

    // ---- epilogue ----
    #pragma unroll
    for (int mi = 0; mi < 2; mi++) {
        const int rbase = tile_m + wm * 32 + mi * 16 + g;
        #pragma unroll
        for (int rr = 0; rr < 2; rr++) {
            const int row = rbase + rr * 8;
            const float* resrow = resid ? resid + (size_t)row * ldres : nullptr;
            float* crow  = C + (size_t)row * ldc;
            float* crrow = Cr ? Cr + (size_t)row * ldc : nullptr;
            #pragma unroll
            for (int ni = 0; ni < 4; ni++) {
                const int c = tile_n + wn * 32 + ni * 8 + tg * 2;
                float v0 = acc[mi][ni][rr * 2 + 0];
                float v1 = acc[mi][ni][rr * 2 + 1];
                if (bias)   { v0 += bias[c];   v1 += bias[c + 1]; }
                if (bias2)  { v0 += bias2[c];  v1 += bias2[c + 1]; }
                if (resrow) { v0 += resrow[c]; v1 += resrow[c + 1]; }
                if (dogelu) { v0 = gelu_exact(v0); v1 = gelu_exact(v1); }
                if (doround){ v0 = tf32r(v0); v1 = tf32r(v1); }
                if (permC) {
                    crow[permcol(c)]     = v0;
                    crow[permcol(c + 1)] = v1;
                } else {
                    *(float2*)(crow + c) = make_float2(v0, v1);
                }
                if (crrow) {
                    crrow[permcol(c)]     = tf32r(v0);
                    crrow[permcol(c + 1)] = tf32r(v1);
                }
            }
        }
    }
}

// ---------------------------------------------------------------------------
// x prepass: round + k-permute (each thread owns one 32-float block)
// ---------------------------------------------------------------------------
__global__ void __launch_bounds__(256)
permute_x(const float* __restrict__ x, float* __restrict__ xr)
{
    size_t idx = (size_t)blockIdx.x * 256 + threadIdx.x;
    const float4* src = (const float4*)(x + idx * 32);
    float4* dst = (float4*)(xr + idx * 32);
    float v[32];
    #pragma unroll
    for (int i = 0; i < 8; i++) {
        float4 u = src[i];
        v[i * 4 + 0] = u.x; v[i * 4 + 1] = u.y;
        v[i * 4 + 2] = u.z; v[i * 4 + 3] = u.w;
    }
    #pragma unroll
    for (int t = 0; t < 8; t++)
        dst[t] = make_float4(tf32r(v[invperm(4 * t)]),
                             tf32r(v[invperm(4 * t + 1)]),
                             tf32r(v[invperm(4 * t + 2)]),
                             tf32r(v[invperm(4 * t + 3)]));
}

// ---------------------------------------------------------------------------
// Weight prepass: ONE launch. W[K,N] -> Wt[N,K], tf32 rounded, k-permuted.
// ---------------------------------------------------------------------------
#define NWT 13
struct TTable {
    const float* W[NWT];
    float*       Wt[NWT];
    int K[NWT], N[NWT], t0[NWT];
};

__global__ void __launch_bounds__(256)
transpose_all(TTable tab)
{
    __shared__ float ts[32][33];
    int bid = blockIdx.x;
    int e = 0;
    #pragma unroll
    for (int i = 1; i < NWT; i++)
        if (bid >= tab.t0[i]) e = i;
    int t  = bid - tab.t0[e];
    int nx = tab.N[e] >> 5;
    int n0 = (t % nx) << 5, k0 = (t / nx) << 5;
    const float* W = tab.W[e];
    float* Wt = tab.Wt[e];
    int K = tab.K[e], N = tab.N[e];
    int tx = threadIdx.x & 31, ty = threadIdx.x >> 5;   // 32 x 8
    #pragma unroll
    for (int j = 0; j < 32; j += 8)
        ts[ty + j][tx] = W[(size_t)(k0 + ty + j) * N + n0 + tx];
    __syncthreads();
    int pp = (tx & 3) * 8 + (tx >> 3) * 2 + ((tx >> 2) & 1);  // permuted pos of k=tx
    #pragma unroll
    for (int j = 0; j < 32; j += 8)
        Wt[(size_t)(n0 + ty + j) * K + k0 + pp] = tf32r(ts[tx][ty + j]);
}

// ---------------------------------------------------------------------------
// LayerNorms (outputs rounded + k-permuted: they always feed GEMM A operands)
// ---------------------------------------------------------------------------
__device__ __forceinline__ void blockreduce2(float& s, float& q, float* red, int nwarps) {
    #pragma unroll
    for (int o = 16; o > 0; o >>= 1) {
        s += __shfl_xor_sync(0xFFFFFFFFu, s, o);
        q += __shfl_xor_sync(0xFFFFFFFFu, q, o);
    }
    int warp = threadIdx.x >> 5, lane = threadIdx.x & 31;
    if (lane == 0) { red[warp] = s; red[warp + 8] = q; }
    __syncthreads();
    s = 0.f; q = 0.f;
    for (int w = 0; w < nwarps; w++) { s += red[w]; q += red[w + 8]; }
}

__global__ void ln512(const float* __restrict__ x, float* __restrict__ y,
                      const float* __restrict__ gam, const float* __restrict__ bet)
{
    __shared__ float red[16];
    int row = blockIdx.x;
    int t = threadIdx.x;                          // 128 threads, float4 each
    const float4* xr = (const float4*)(x + (size_t)row * DMODEL);
    float4 a = xr[t];
    float s = a.x + a.y + a.z + a.w;
    float q = a.x * a.x + a.y * a.y + a.z * a.z + a.w * a.w;
    blockreduce2(s, q, red, 4);
    float m  = s * (1.f / DMODEL);
    float va = q * (1.f / DMODEL) - m * m;
    float rs = rsqrtf(va + 1e-5f);
    float4 gg = ((const float4*)gam)[t];
    float4 bb = ((const float4*)bet)[t];
    float o[4];
    o[0] = tf32r((a.x - m) * rs * gg.x + bb.x);
    o[1] = tf32r((a.y - m) * rs * gg.y + bb.y);
    o[2] = tf32r((a.z - m) * rs * gg.z + bb.z);
    o[3] = tf32r((a.w - m) * rs * gg.w + bb.w);
    float* yr = y + (size_t)row * DMODEL;
    #pragma unroll
    for (int i = 0; i < 4; i++) yr[permcol(t * 4 + i)] = o[i];
}

__global__ void head_gelu_ln(const float* __restrict__ z, float* __restrict__ y,
                             const float* __restrict__ gam, const float* __restrict__ bet)
{
    __shared__ float red[16];
    int b = blockIdx.x, h = blockIdx.y;
    int c = threadIdx.x;                           // 256 threads
    int base = b * (NHEAD * HDIM) + h * HDIM;
    float v = gelu_exact(z[base + c]);
    float s = v, q = v * v;
    blockreduce2(s, q, red, 8);
    float m  = s * (1.f / HDIM);
    float va = q * (1.f / HDIM) - m * m;
    float rs = rsqrtf(va + 1e-5f);
    float o = tf32r((v - m) * rs * gam[h * HDIM + c] + bet[h * HDIM + c]);
    y[base + permcol(c)] = o;
}

// ---------------------------------------------------------------------------
// Launch
// ---------------------------------------------------------------------------
extern "C" void kernel_launch(void* const* d_in, const int* in_sizes, int n_in,
                              void* d_out, int out_size)
{
    (void)in_sizes; (void)n_in; (void)out_size;
    const float* x       = (const float*)d_in[0];
    const float* w_in    = (const float*)d_in[1];
    const float* b_in    = (const float*)d_in[2];
    const float* pos     = (const float*)d_in[3];
    const float* ln1_g   = (const float*)d_in[4];
    const float* ln1_b   = (const float*)d_in[5];
    const float* wv_sa   = (const float*)d_in[6];
    const float* bv_sa   = (const float*)d_in[7];
    const float* wo_sa   = (const float*)d_in[8];
    const float* bo_sa   = (const float*)d_in[9];
    const float* wv_ca   = (const float*)d_in[12];
    const float* bv_ca   = (const float*)d_in[13];
    const float* wo_ca   = (const float*)d_in[14];
    const float* bo_ca   = (const float*)d_in[15];
    const float* ln3_g   = (const float*)d_in[16];
    const float* ln3_b   = (const float*)d_in[17];
    const float* w_ff1   = (const float*)d_in[18];
    const float* b_ff1   = (const float*)d_in[19];
    const float* w_ff2   = (const float*)d_in[20];
    const float* b_ff2   = (const float*)d_in[21];
    const float* lnout_g = (const float*)d_in[22];
    const float* lnout_b = (const float*)d_in[23];
    const float* wh1     = (const float*)d_in[24];
    const float* bh1     = (const float*)d_in[25];
    const float* lnh_g   = (const float*)d_in[26];
    const float* lnh_b   = (const float*)d_in[27];
    const float* wh2     = (const float*)d_in[28];
    const float* bh2     = (const float*)d_in[29];
    float* out = (float*)d_out;

    float *xr, *h0, *h0r, *h, *lnb, *t, *ff, *z, *z2, *wt;
    cudaGetSymbolAddress((void**)&xr,  g_xr);
    cudaGetSymbolAddress((void**)&h0,  g_h0);
    cudaGetSymbolAddress((void**)&h0r, g_h0r);
    cudaGetSymbolAddress((void**)&h,   g_h);
    cudaGetSymbolAddress((void**)&lnb, g_lnb);
    cudaGetSymbolAddress((void**)&t,   g_t);
    cudaGetSymbolAddress((void**)&ff,  g_ff);
    cudaGetSymbolAddress((void**)&z,   g_z);
    cudaGetSymbolAddress((void**)&z2,  g_z2);
    cudaGetSymbolAddress((void**)&wt,  g_wt);

    cudaFuncSetAttribute(gemm_mma,
                         cudaFuncAttributeMaxDynamicSharedMemorySize, SMEM_BYTES);

    // ---- prepasses ----
    permute_x<<<(BATCH * DIN / 32) / 256, 256>>>(x, xr);
    {
        TTable tab;
        int idx = 0, acc = 0;
        auto add = [&](const float* W, float* Wt, int K, int N) {
            tab.W[idx] = W; tab.Wt[idx] = Wt; tab.K[idx] = K; tab.N[idx] = N;
            tab.t0[idx] = acc; acc += (K / 32) * (N / 32); idx++;
        };
        add(w_in,  wt + OFF_WIN,  DIN,    DMODEL);
        add(wv_sa, wt + OFF_WVSA, DMODEL, DMODEL);
        add(wo_sa, wt + OFF_WOSA, DMODEL, DMODEL);
        add(wv_ca, wt + OFF_WVCA, DMODEL, DMODEL);
        add(wo_ca, wt + OFF_WOCA, DMODEL, DMODEL);
        add(w_ff1, wt + OFF_FF1,  DMODEL, DFF);
        add(w_ff2, wt + OFF_FF2,  DFF,    DMODEL);
        for (int hh = 0; hh < NHEAD; hh++)
            add(wh1 + (size_t)hh * DMODEL * HDIM,
                wt + OFF_WH1 + (size_t)hh * HDIM * DMODEL, DMODEL, HDIM);
        for (int hh = 0; hh < NHEAD; hh++)
            add(wh2 + (size_t)hh * HDIM * OUTD,
                wt + OFF_WH2 + (size_t)hh * OUTD * HDIM, HDIM, OUTD);
        transpose_all<<<acc, 256>>>(tab);
    }

    auto G = [&](const float* A, int lda, int az,
                 const float* Bt, int K, int bz,
                 float* C, int ldc, int cz, float* Cr,
                 const float* b1, int b1z, const float* b2,
                 const float* res, int ldres,
                 int dg, int dr, int pc, int M, int N, int nz) {
        dim3 grid(N / BN, M / BM, nz);
        gemm_mma<<<grid, NTH, SMEM_BYTES>>>(A, lda, az, Bt, K, bz,
            C, ldc, cz, Cr, b1, b1z, b2, res, ldres, dg, dr, pc);
    };

    // 1. h0 = x @ w_in + b_in + pos;  h0r = rounded+permuted copy
    G(xr, DIN, 0, wt + OFF_WIN, DIN, 0, h0, DMODEL, 0, h0r,
      b_in, 0, pos, nullptr, 0, 0, 0, 0, BATCH, DMODEL, 1);
    // 2. lnb = LN(h0; ln1)  (rounded + permuted)
    ln512<<<BATCH, 128>>>(h0, lnb, ln1_g, ln1_b);
    // 3. t = lnb @ wv_sa + bv_sa  (rounded + permuted)
    G(lnb, DMODEL, 0, wt + OFF_WVSA, DMODEL, 0, t, DMODEL, 0, nullptr,
      bv_sa, 0, nullptr, nullptr, 0, 0, 1, 1, BATCH, DMODEL, 1);
    // 4. h = h0 + t @ wo_sa + bo_sa  (plain)
    G(t, DMODEL, 0, wt + OFF_WOSA, DMODEL, 0, h, DMODEL, 0, nullptr,
      bo_sa, 0, nullptr, h0, DMODEL, 0, 0, 0, BATCH, DMODEL, 1);
    // 5. t = h0r @ wv_ca + bv_ca  (rounded + permuted)
    G(h0r, DMODEL, 0, wt + OFF_WVCA, DMODEL, 0, t, DMODEL, 0, nullptr,
      bv_ca, 0, nullptr, nullptr, 0, 0, 1, 1, BATCH, DMODEL, 1);
    // 6. h = h + t @ wo_ca + bo_ca  (in-place residual: same elem, same thread)
    G(t, DMODEL, 0, wt + OFF_WOCA, DMODEL, 0, h, DMODEL, 0, nullptr,
      bo_ca, 0, nullptr, h, DMODEL, 0, 0, 0, BATCH, DMODEL, 1);
    // 7. lnb = LN(h; ln3)
    ln512<<<BATCH, 128>>>(h, lnb, ln3_g, ln3_b);
    // 8. ff = gelu(lnb @ w_ff1 + b_ff1)  (rounded + permuted)
    G(lnb, DMODEL, 0, wt + OFF_FF1, DMODEL, 0, ff, DFF, 0, nullptr,
      b_ff1, 0, nullptr, nullptr, 0, 1, 1, 1, BATCH, DFF, 1);
    // 9. h = h + ff @ w_ff2 + b_ff2  (plain)
    G(ff, DFF, 0, wt + OFF_FF2, DFF, 0, h, DMODEL, 0, nullptr,
      b_ff2, 0, nullptr, h, DMODEL, 0, 0, 0, BATCH, DMODEL, 1);
    // 10. lnb = LN(h; lnout)
    ln512<<<BATCH, 128>>>(h, lnb, lnout_g, lnout_b);
    // 11. z[:, hh] = lnb @ wh1[hh] + bh1[hh]  — batched over heads (plain out)
    G(lnb, DMODEL, 0, wt + OFF_WH1, DMODEL, HDIM * DMODEL,
      z, NHEAD * HDIM, HDIM, nullptr,
      bh1, HDIM, nullptr, nullptr, 0, 0, 0, 0, BATCH, HDIM, NHEAD);
    // 12. z2 = LN(gelu(z)) per head  (rounded + permuted)
    head_gelu_ln<<<dim3(BATCH, NHEAD), 256>>>(z, z2, lnh_g, lnh_b);
    // 13. out[:, hh, :] = z2[:, hh] @ wh2[hh] + bh2[hh]  — batched (plain out)
    G(z2, NHEAD * HDIM, HDIM, wt + OFF_WH2, HDIM, OUTD * HDIM,
      out, NHEAD * OUTD, OUTD, nullptr,
      bh2, OUTD, nullptr, nullptr, 0, 0, 0, 0, BATCH, OUTD, NHEAD);
}

// round 12
// speedup vs baseline: 1.2599x; 1.2599x over previous
#include <cuda_runtime.h>
#include <math.h>
#include <stdint.h>

// ---------------------------------------------------------------------------
// Problem constants
// ---------------------------------------------------------------------------
#define BATCH 8192
#define DIN   4096
#define DMODEL 512
#define DFF   2048
#define NHEAD 3
#define HDIM  256
#define OUTD  896

// ---------------------------------------------------------------------------
// HMMA tf32 GEMM tiling: 128x64x32, 256 threads, warp tile 32x32, 2 CTAs/SM
// ---------------------------------------------------------------------------
#define BM 128
#define BN 64
#define BK 32
#define NSTAGE 4
#define NTH 256
#define TILE_A_F 4096          // 128*32
#define TILE_B_F 2048          // 64*32
#define STAGE_F  (TILE_A_F + TILE_B_F)
#define SMEM_BYTES (NSTAGE * STAGE_F * 4)   // 98304 -> 2 CTAs/SM

// ---------------------------------------------------------------------------
// Scratch (device globals; no allocation allowed)
// ---------------------------------------------------------------------------
__device__ float g_xr [BATCH * DIN];      // rounded + k-permuted copy of x
__device__ float g_h0 [BATCH * DMODEL];
__device__ float g_h0r[BATCH * DMODEL];   // permuted+rounded copy of h0
__device__ float g_h  [BATCH * DMODEL];
__device__ float g_lnb[BATCH * DMODEL];   // permuted
__device__ float g_t  [BATCH * DMODEL];   // permuted
__device__ float g_ff [BATCH * DFF];      // permuted
__device__ float g_z  [BATCH * NHEAD * HDIM];
__device__ float g_z2 [BATCH * NHEAD * HDIM];  // permuted

// transposed + tf32-rounded + k-permuted weights [N,K]
#define OFF_WIN  0
#define OFF_WVSA 2097152
#define OFF_WOSA 2359296
#define OFF_WVCA 2621440
#define OFF_WOCA 2883584
#define OFF_FF1  3145728
#define OFF_FF2  4194304
#define OFF_WH1  5242880
#define OFF_WH2  5636096
#define WT_TOTAL 6324224
__device__ float g_wt[WT_TOTAL];

// ---------------------------------------------------------------------------
// Helpers
// ---------------------------------------------------------------------------
__device__ __forceinline__ float tf32r(float f) {
    unsigned u;
    asm("cvt.rna.tf32.f32 %0, %1;" : "=r"(u) : "f"(f));
    return __uint_as_float(u);
}
__device__ __forceinline__ unsigned f2u(float f) { return __float_as_uint(f); }

__device__ __forceinline__ float gelu_exact(float v) {
    return 0.5f * v * (1.0f + erff(v * 0.7071067811865476f));
}

// permuted position of column/k index c within its 32-block:
// p = (c%4)*8 + ((c%32)/8)*2 + ((c/4)%2)
__device__ __forceinline__ int permcol(int c) {
    return (c & ~31) + ((c & 3) * 8 + ((c & 31) >> 3) * 2 + ((c >> 2) & 1));
}
// inverse within a 32-block: source index for permuted position p
__device__ __forceinline__ int invperm(int p) {
    return (p >> 3) + (((p >> 1) & 3) << 3) + ((p & 1) << 2);
}

__device__ __forceinline__ uint32_t smem_u32(const void* p) {
    uint32_t a;
    asm("{ .reg .u64 t; cvta.to.shared.u64 t, %1; cvt.u32.u64 %0, t; }" : "=r"(a) : "l"(p));
    return a;
}
__device__ __forceinline__ void cp16(uint32_t s, const void* g) {
    asm volatile("cp.async.cg.shared.global [%0], [%1], 16;" :: "r"(s), "l"(g) : "memory");
}

#define MMA(d, a0,a1,a2,a3, b0,b1) \
    asm volatile("mma.sync.aligned.m16n8k8.row.col.f32.tf32.tf32.f32 " \
        "{%0,%1,%2,%3},{%4,%5,%6,%7},{%8,%9},{%0,%1,%2,%3};" \
        : "+f"((d)[0]), "+f"((d)[1]), "+f"((d)[2]), "+f"((d)[3]) \
        : "r"(a0), "r"(a1), "r"(a2), "r"(a3), "r"(b0), "r"(b1))

// ---------------------------------------------------------------------------
// tf32 GEMM via mma.sync: C[M,N] = A[M,K] @ Bt[N,K]^T
// A and Bt both tf32-rounded and k-permuted within 32-blocks.
// Epilogue: +bias(+z-stride) +bias2 +resid, optional gelu / tf32 round,
// output plain or permuted, optional second permuted+rounded copy Cr.
// ---------------------------------------------------------------------------
__global__ void __launch_bounds__(NTH, 2)
gemm_mma(const float* __restrict__ A, int lda, int az,
         const float* __restrict__ Bt, int K, int bz,
         float* __restrict__ C, int ldc, int cz,
         float* __restrict__ Cr,
         const float* __restrict__ bias, int biasz,
         const float* __restrict__ bias2,
         const float* __restrict__ resid, int ldres,
         int dogelu, int doround, int permC)
{
    extern __shared__ float smemf[];
    const uint32_t sb = smem_u32(smemf);

    A  += (size_t)blockIdx.z * az;
    Bt += (size_t)blockIdx.z * bz;
    C  += (size_t)blockIdx.z * cz;
    if (bias) bias += (size_t)blockIdx.z * biasz;

    const int tid = threadIdx.x;
    const int wid = tid >> 5, lane = tid & 31;
    const int g = lane >> 2, tg = lane & 3;
    const int wm = wid & 3, wn = wid >> 2;        // 4x2 warp grid
    const int tile_m = blockIdx.y * BM;
    const int tile_n = blockIdx.x * BN;
    const int ktiles = K / BK;

    float acc[2][4][4];
    #pragma unroll
    for (int i = 0; i < 2; i++)
        #pragma unroll
        for (int j = 0; j < 4; j++)
            #pragma unroll
            for (int r = 0; r < 4; r++) acc[i][j][r] = 0.f;

    auto load_stage = [&](int buf, int k0) {
        // A: 128x32 floats = 1024 float4, 4 per thread
        #pragma unroll
        for (int i = 0; i < 4; i++) {
            int idx = tid + i * NTH;
            int r = idx >> 3, q = idx & 7;
            uint32_t dst = sb + (buf * STAGE_F + r * 32 + ((q ^ (r & 7)) * 4)) * 4;
            cp16(dst, A + (size_t)(tile_m + r) * lda + k0 + q * 4);
        }
        // B: 64x32 floats = 512 float4, 2 per thread
        #pragma unroll
        for (int i = 0; i < 2; i++) {
            int idx = tid + i * NTH;
            int r = idx >> 3, q = idx & 7;
            uint32_t dst = sb + (buf * STAGE_F + TILE_A_F + r * 32 + ((q ^ (r & 7)) * 4)) * 4;
            cp16(dst, Bt + (size_t)(tile_n + r) * K + k0 + q * 4);
        }
    };

    // ---- prologue: stages 0, 1 ----
    load_stage(0, 0);
    asm volatile("cp.async.commit_group;" ::: "memory");
    load_stage(1, BK);
    asm volatile("cp.async.commit_group;" ::: "memory");

    // ---- main loop ----
    for (int kt = 0; kt < ktiles; kt++) {
        asm volatile("cp.async.wait_group 1;" ::: "memory");
        __syncthreads();

        const float* as = smemf + (kt % NSTAGE) * STAGE_F;
        const float* bs = as + TILE_A_F;

        // ---- half 0: fragments ----
        float4 af0[2][2], bf0[4];
        {
            const int gsw = ((2 * tg + 0) ^ g) * 4;
            #pragma unroll
            for (int mi = 0; mi < 2; mi++) {
                const int r0 = wm * 32 + mi * 16 + g;
                af0[mi][0] = *(const float4*)(as + r0 * 32 + gsw);
                af0[mi][1] = *(const float4*)(as + (r0 + 8) * 32 + gsw);
            }
            #pragma unroll
            for (int ni = 0; ni < 4; ni++) {
                const int n0 = wn * 32 + ni * 8 + g;
                bf0[ni] = *(const float4*)(bs + n0 * 32 + gsw);
            }
        }

        // prefetch stage kt+2 now — half 0+1 MMAs cover its latency
        const int pf = kt + 2;
        if (pf < ktiles) load_stage(pf % NSTAGE, pf * BK);
        asm volatile("cp.async.commit_group;" ::: "memory");

        #pragma unroll
        for (int ni = 0; ni < 4; ni++)
            #pragma unroll
            for (int mi = 0; mi < 2; mi++) {
                MMA(acc[mi][ni],
                    f2u(af0[mi][0].x), f2u(af0[mi][1].x),
                    f2u(af0[mi][0].y), f2u(af0[mi][1].y),
                    f2u(bf0[ni].x), f2u(bf0[ni].y));
                MMA(acc[mi][ni],
                    f2u(af0[mi][0].z), f2u(af0[mi][1].z),
                    f2u(af0[mi][0].w), f2u(af0[mi][1].w),
                    f2u(bf0[ni].z), f2u(bf0[ni].w));
            }

        // ---- half 1: fragments + MMAs ----
        float4 af1[2][2], bf1[4];
        {
            const int gsw = ((2 * tg + 1) ^ g) * 4;
            #pragma unroll
            for (int mi = 0; mi < 2; mi++) {
                const int r0 = wm * 32 + mi * 16 + g;
                af1[mi][0] = *(const float4*)(as + r0 * 32 + gsw);
                af1[mi][1] = *(const float4*)(as + (r0 + 8) * 32 + gsw);
            }
            #pragma unroll
            for (int ni = 0; ni < 4; ni++) {
                const int n0 = wn * 32 + ni * 8 + g;
                bf1[ni] = *(const float4*)(bs + n0 * 32 + gsw);
            }
        }
        #pragma unroll
        for (int ni = 0; ni < 4; ni++)
            #pragma unroll
            for (int mi = 0; mi < 2; mi++) {
                MMA(acc[mi][ni],
                    f2u(af1[mi][0].x), f2u(af1[mi][1].x),
                    f2u(af1[mi][0].y), f2u(af1[mi][1].y),
                    f2u(bf1[ni].x), f2u(bf1[ni].y));
                MMA(acc[mi][ni],
                    f2u(af1[mi][0].z), f2u(af1[mi][1].z),
                    f2u(af1[mi][0].w), f2u(af1[mi][1].w),
                    f2u(bf1[ni].z), f2u(bf1[ni].w));
            }
    }

    // ---- epilogue ----
    #pragma unroll
    for (int mi = 0; mi < 2; mi++) {
        const int rbase = tile_m + wm * 32 + mi * 16 + g;
        #pragma unroll
        for (int rr = 0; rr < 2; rr++) {
            const int row = rbase + rr * 8;
            const float* resrow = resid ? resid + (size_t)row * ldres : nullptr;
            float* crow  = C + (size_t)row * ldc;
            float* crrow = Cr ? Cr + (size_t)row * ldc : nullptr;
            #pragma unroll
            for (int ni = 0; ni < 4; ni++) {
                const int c = tile_n + wn * 32 + ni * 8 + tg * 2;
                float v0 = acc[mi][ni][rr * 2 + 0];
                float v1 = acc[mi][ni][rr * 2 + 1];
                if (bias)   { v0 += bias[c];   v1 += bias[c + 1]; }
                if (bias2)  { v0 += bias2[c];  v1 += bias2[c + 1]; }
                if (resrow) { v0 += resrow[c]; v1 += resrow[c + 1]; }
                if (dogelu) { v0 = gelu_exact(v0); v1 = gelu_exact(v1); }
                if (doround){ v0 = tf32r(v0); v1 = tf32r(v1); }
                if (permC) {
                    crow[permcol(c)]     = v0;
                    crow[permcol(c + 1)] = v1;
                } else {
                    *(float2*)(crow + c) = make_float2(v0, v1);
                }
                if (crrow) {
                    crrow[permcol(c)]     = tf32r(v0);
                    crrow[permcol(c + 1)] = tf32r(v1);
                }
            }
        }
    }
}

// ---------------------------------------------------------------------------
// x prepass: round + k-permute (each thread owns one 32-float block)
// ---------------------------------------------------------------------------
__global__ void __launch_bounds__(256)
permute_x(const float* __restrict__ x, float* __restrict__ xr)
{
    size_t idx = (size_t)blockIdx.x * 256 + threadIdx.x;
    const float4* src = (const float4*)(x + idx * 32);
    float4* dst = (float4*)(xr + idx * 32);
    float v[32];
    #pragma unroll
    for (int i = 0; i < 8; i++) {
        float4 u = src[i];
        v[i * 4 + 0] = u.x; v[i * 4 + 1] = u.y;
        v[i * 4 + 2] = u.z; v[i * 4 + 3] = u.w;
    }
    #pragma unroll
    for (int t = 0; t < 8; t++)
        dst[t] = make_float4(tf32r(v[invperm(4 * t)]),
                             tf32r(v[invperm(4 * t + 1)]),
                             tf32r(v[invperm(4 * t + 2)]),
                             tf32r(v[invperm(4 * t + 3)]));
}

// ---------------------------------------------------------------------------
// Weight prepass: ONE launch. W[K,N] -> Wt[N,K], tf32 rounded, k-permuted.
// ---------------------------------------------------------------------------
#define NWT 13
struct TTable {
    const float* W[NWT];
    float*       Wt[NWT];
    int K[NWT], N[NWT], t0[NWT];
};

__global__ void __launch_bounds__(256)
transpose_all(TTable tab)
{
    __shared__ float ts[32][33];
    int bid = blockIdx.x;
    int e = 0;
    #pragma unroll
    for (int i = 1; i < NWT; i++)
        if (bid >= tab.t0[i]) e = i;
    int t  = bid - tab.t0[e];
    int nx = tab.N[e] >> 5;
    int n0 = (t % nx) << 5, k0 = (t / nx) << 5;
    const float* W = tab.W[e];
    float* Wt = tab.Wt[e];
    int K = tab.K[e], N = tab.N[e];
    int tx = threadIdx.x & 31, ty = threadIdx.x >> 5;   // 32 x 8
    #pragma unroll
    for (int j = 0; j < 32; j += 8)
        ts[ty + j][tx] = W[(size_t)(k0 + ty + j) * N + n0 + tx];
    __syncthreads();
    int pp = (tx & 3) * 8 + (tx >> 3) * 2 + ((tx >> 2) & 1);  // permuted pos of k=tx
    #pragma unroll
    for (int j = 0; j < 32; j += 8)
        Wt[(size_t)(n0 + ty + j) * K + k0 + pp] = tf32r(ts[tx][ty + j]);
}

// ---------------------------------------------------------------------------
// LayerNorms (outputs rounded + k-permuted: they always feed GEMM A operands)
// ---------------------------------------------------------------------------
__device__ __forceinline__ void blockreduce2(float& s, float& q, float* red, int nwarps) {
    #pragma unroll
    for (int o = 16; o > 0; o >>= 1) {
        s += __shfl_xor_sync(0xFFFFFFFFu, s, o);
        q += __shfl_xor_sync(0xFFFFFFFFu, q, o);
    }
    int warp = threadIdx.x >> 5, lane = threadIdx.x & 31;
    if (lane == 0) { red[warp] = s; red[warp + 8] = q; }
    __syncthreads();
    s = 0.f; q = 0.f;
    for (int w = 0; w < nwarps; w++) { s += red[w]; q += red[w + 8]; }
}

__global__ void ln512(const float* __restrict__ x, float* __restrict__ y,
                      const float* __restrict__ gam, const float* __restrict__ bet)
{
    __shared__ float red[16];
    int row = blockIdx.x;
    int t = threadIdx.x;                          // 128 threads, float4 each
    const float4* xr = (const float4*)(x + (size_t)row * DMODEL);
    float4 a = xr[t];
    float s = a.x + a.y + a.z + a.w;
    float q = a.x * a.x + a.y * a.y + a.z * a.z + a.w * a.w;
    blockreduce2(s, q, red, 4);
    float m  = s * (1.f / DMODEL);
    float va = q * (1.f / DMODEL) - m * m;
    float rs = rsqrtf(va + 1e-5f);
    float4 gg = ((const float4*)gam)[t];
    float4 bb = ((const float4*)bet)[t];
    float o[4];
    o[0] = tf32r((a.x - m) * rs * gg.x + bb.x);
    o[1] = tf32r((a.y - m) * rs * gg.y + bb.y);
    o[2] = tf32r((a.z - m) * rs * gg.z + bb.z);
    o[3] = tf32r((a.w - m) * rs * gg.w + bb.w);
    float* yr = y + (size_t)row * DMODEL;
    #pragma unroll
    for (int i = 0; i < 4; i++) yr[permcol(t * 4 + i)] = o[i];
}

__global__ void head_gelu_ln(const float* __restrict__ z, float* __restrict__ y,
                             const float* __restrict__ gam, const float* __restrict__ bet)
{
    __shared__ float red[16];
    int b = blockIdx.x, h = blockIdx.y;
    int c = threadIdx.x;                           // 256 threads
    int base = b * (NHEAD * HDIM) + h * HDIM;
    float v = gelu_exact(z[base + c]);
    float s = v, q = v * v;
    blockreduce2(s, q, red, 8);
    float m  = s * (1.f / HDIM);
    float va = q * (1.f / HDIM) - m * m;
    float rs = rsqrtf(va + 1e-5f);
    float o = tf32r((v - m) * rs * gam[h * HDIM + c] + bet[h * HDIM + c]);
    y[base + permcol(c)] = o;
}

// ---------------------------------------------------------------------------
// Launch
// ---------------------------------------------------------------------------
extern "C" void kernel_launch(void* const* d_in, const int* in_sizes, int n_in,
                              void* d_out, int out_size)
{
    (void)in_sizes; (void)n_in; (void)out_size;
    const float* x       = (const float*)d_in[0];
    const float* w_in    = (const float*)d_in[1];
    const float* b_in    = (const float*)d_in[2];
    const float* pos     = (const float*)d_in[3];
    const float* ln1_g   = (const float*)d_in[4];
    const float* ln1_b   = (const float*)d_in[5];
    const float* wv_sa   = (const float*)d_in[6];
    const float* bv_sa   = (const float*)d_in[7];
    const float* wo_sa   = (const float*)d_in[8];
    const float* bo_sa   = (const float*)d_in[9];
    const float* wv_ca   = (const float*)d_in[12];
    const float* bv_ca   = (const float*)d_in[13];
    const float* wo_ca   = (const float*)d_in[14];
    const float* bo_ca   = (const float*)d_in[15];
    const float* ln3_g   = (const float*)d_in[16];
    const float* ln3_b   = (const float*)d_in[17];
    const float* w_ff1   = (const float*)d_in[18];
    const float* b_ff1   = (const float*)d_in[19];
    const float* w_ff2   = (const float*)d_in[20];
    const float* b_ff2   = (const float*)d_in[21];
    const float* lnout_g = (const float*)d_in[22];
    const float* lnout_b = (const float*)d_in[23];
    const float* wh1     = (const float*)d_in[24];
    const float* bh1     = (const float*)d_in[25];
    const float* lnh_g   = (const float*)d_in[26];
    const float* lnh_b   = (const float*)d_in[27];
    const float* wh2     = (const float*)d_in[28];
    const float* bh2     = (const float*)d_in[29];
    float* out = (float*)d_out;

    float *xr, *h0, *h0r, *h, *lnb, *t, *ff, *z, *z2, *wt;
    cudaGetSymbolAddress((void**)&xr,  g_xr);
    cudaGetSymbolAddress((void**)&h0,  g_h0);
    cudaGetSymbolAddress((void**)&h0r, g_h0r);
    cudaGetSymbolAddress((void**)&h,   g_h);
    cudaGetSymbolAddress((void**)&lnb, g_lnb);
    cudaGetSymbolAddress((void**)&t,   g_t);
    cudaGetSymbolAddress((void**)&ff,  g_ff);
    cudaGetSymbolAddress((void**)&z,   g_z);
    cudaGetSymbolAddress((void**)&z2,  g_z2);
    cudaGetSymbolAddress((void**)&wt,  g_wt);

    cudaFuncSetAttribute(gemm_mma,
                         cudaFuncAttributeMaxDynamicSharedMemorySize, SMEM_BYTES);

    // ---- prepasses ----
    permute_x<<<(BATCH * DIN / 32) / 256, 256>>>(x, xr);
    {
        TTable tab;
        int idx = 0, acc = 0;
        auto add = [&](const float* W, float* Wt, int K, int N) {
            tab.W[idx] = W; tab.Wt[idx] = Wt; tab.K[idx] = K; tab.N[idx] = N;
            tab.t0[idx] = acc; acc += (K / 32) * (N / 32); idx++;
        };
        add(w_in,  wt + OFF_WIN,  DIN,    DMODEL);
        add(wv_sa, wt + OFF_WVSA, DMODEL, DMODEL);
        add(wo_sa, wt + OFF_WOSA, DMODEL, DMODEL);
        add(wv_ca, wt + OFF_WVCA, DMODEL, DMODEL);
        add(wo_ca, wt + OFF_WOCA, DMODEL, DMODEL);
        add(w_ff1, wt + OFF_FF1,  DMODEL, DFF);
        add(w_ff2, wt + OFF_FF2,  DFF,    DMODEL);
        for (int hh = 0; hh < NHEAD; hh++)
            add(wh1 + (size_t)hh * DMODEL * HDIM,
                wt + OFF_WH1 + (size_t)hh * HDIM * DMODEL, DMODEL, HDIM);
        for (int hh = 0; hh < NHEAD; hh++)
            add(wh2 + (size_t)hh * HDIM * OUTD,
                wt + OFF_WH2 + (size_t)hh * OUTD * HDIM, HDIM, OUTD);
        transpose_all<<<acc, 256>>>(tab);
    }

    auto G = [&](const float* A, int lda, int az,
                 const float* Bt, int K, int bz,
                 float* C, int ldc, int cz, float* Cr,
                 const float* b1, int b1z, const float* b2,
                 const float* res, int ldres,
                 int dg, int dr, int pc, int M, int N, int nz) {
        dim3 grid(N / BN, M / BM, nz);
        gemm_mma<<<grid, NTH, SMEM_BYTES>>>(A, lda, az, Bt, K, bz,
            C, ldc, cz, Cr, b1, b1z, b2, res, ldres, dg, dr, pc);
    };

    // 1. h0 = x @ w_in + b_in + pos;  h0r = rounded+permuted copy
    G(xr, DIN, 0, wt + OFF_WIN, DIN, 0, h0, DMODEL, 0, h0r,
      b_in, 0, pos, nullptr, 0, 0, 0, 0, BATCH, DMODEL, 1);
    // 2. lnb = LN(h0; ln1)  (rounded + permuted)
    ln512<<<BATCH, 128>>>(h0, lnb, ln1_g, ln1_b);
    // 3. t = lnb @ wv_sa + bv_sa  (rounded + permuted)
    G(lnb, DMODEL, 0, wt + OFF_WVSA, DMODEL, 0, t, DMODEL, 0, nullptr,
      bv_sa, 0, nullptr, nullptr, 0, 0, 1, 1, BATCH, DMODEL, 1);
    // 4. h = h0 + t @ wo_sa + bo_sa  (plain)
    G(t, DMODEL, 0, wt + OFF_WOSA, DMODEL, 0, h, DMODEL, 0, nullptr,
      bo_sa, 0, nullptr, h0, DMODEL, 0, 0, 0, BATCH, DMODEL, 1);
    // 5. t = h0r @ wv_ca + bv_ca  (rounded + permuted)
    G(h0r, DMODEL, 0, wt + OFF_WVCA, DMODEL, 0, t, DMODEL, 0, nullptr,
      bv_ca, 0, nullptr, nullptr, 0, 0, 1, 1, BATCH, DMODEL, 1);
    // 6. h = h + t @ wo_ca + bo_ca  (in-place residual: same elem, same thread)
    G(t, DMODEL, 0, wt + OFF_WOCA, DMODEL, 0, h, DMODEL, 0, nullptr,
      bo_ca, 0, nullptr, h, DMODEL, 0, 0, 0, BATCH, DMODEL, 1);
    // 7. lnb = LN(h; ln3)
    ln512<<<BATCH, 128>>>(h, lnb, ln3_g, ln3_b);
    // 8. ff = gelu(lnb @ w_ff1 + b_ff1)  (rounded + permuted)
    G(lnb, DMODEL, 0, wt + OFF_FF1, DMODEL, 0, ff, DFF, 0, nullptr,
      b_ff1, 0, nullptr, nullptr, 0, 1, 1, 1, BATCH, DFF, 1);
    // 9. h = h + ff @ w_ff2 + b_ff2  (plain)
    G(ff, DFF, 0, wt + OFF_FF2, DFF, 0, h, DMODEL, 0, nullptr,
      b_ff2, 0, nullptr, h, DMODEL, 0, 0, 0, BATCH, DMODEL, 1);
    // 10. lnb = LN(h; lnout)
    ln512<<<BATCH, 128>>>(h, lnb, lnout_g, lnout_b);
    // 11. z[:, hh] = lnb @ wh1[hh] + bh1[hh]  — batched over heads (plain out)
    G(lnb, DMODEL, 0, wt + OFF_WH1, DMODEL, HDIM * DMODEL,
      z, NHEAD * HDIM, HDIM, nullptr,
      bh1, HDIM, nullptr, nullptr, 0, 0, 0, 0, BATCH, HDIM, NHEAD);
    // 12. z2 = LN(gelu(z)) per head  (rounded + permuted)
    head_gelu_ln<<<dim3(BATCH, NHEAD), 256>>>(z, z2, lnh_g, lnh_b);
    // 13. out[:, hh, :] = z2[:, hh] @ wh2[hh] + bh2[hh]  — batched (plain out)
    G(z2, NHEAD * HDIM, HDIM, wt + OFF_WH2, HDIM, OUTD * HDIM,
      out, NHEAD * OUTD, OUTD, nullptr,
      bh2, OUTD, nullptr, nullptr, 0, 0, 0, 0, BATCH, OUTD, NHEAD);
}

// round 13
// speedup vs baseline: 2.0179x; 1.6017x over previous
#include <cuda_runtime.h>
#include <cuda_fp16.h>
#include <math.h>
#include <stdint.h>

// ---------------------------------------------------------------------------
// Problem constants
// ---------------------------------------------------------------------------
#define BATCH 8192
#define DIN   4096
#define DMODEL 512
#define DFF   2048
#define NHEAD 3
#define HDIM  256
#define OUTD  896

// ---------------------------------------------------------------------------
// HMMA fp16 GEMM tiling: 128x64x32, 256 threads, warp tile 32x32, 2 CTAs/SM
// ---------------------------------------------------------------------------
#define BM 128
#define BN 64
#define BK 32                   // halves per k-tile
#define NSTAGE 4
#define NTH 256
#define A_TILE_BYTES 8192       // 128 rows x 64 B
#define B_TILE_BYTES 4096       // 64 rows x 64 B
#define STAGE_BYTES  (A_TILE_BYTES + B_TILE_BYTES)   // 12288
#define SMEM_BYTES   (NSTAGE * STAGE_BYTES)          // 49152 -> 2 CTAs/SM

// ---------------------------------------------------------------------------
// Scratch (device globals; no allocation allowed)
// ---------------------------------------------------------------------------
__device__ __half g_xh  [BATCH * DIN];        // fp16 + pair-permuted x
__device__ float  g_h0  [BATCH * DMODEL];
__device__ __half g_h0rh[BATCH * DMODEL];     // fp16 permuted copy of h0
__device__ float  g_h   [BATCH * DMODEL];
__device__ __half g_lnbh[BATCH * DMODEL];     // fp16 permuted LN outputs
__device__ __half g_th  [BATCH * DMODEL];     // fp16 permuted V outputs
__device__ __half g_ffh [BATCH * DFF];        // fp16 permuted gelu(ff1)
__device__ float  g_z   [BATCH * NHEAD * HDIM];
__device__ __half g_z2h [BATCH * NHEAD * HDIM];  // fp16 permuted head LN

// transposed + fp16 + pair-permuted weights [N,K]
#define OFF_WIN  0
#define OFF_WVSA 2097152
#define OFF_WOSA 2359296
#define OFF_WVCA 2621440
#define OFF_WOCA 2883584
#define OFF_FF1  3145728
#define OFF_FF2  4194304
#define OFF_WH1  5242880
#define OFF_WH2  5636096
#define WT_TOTAL 6324224
__device__ __half g_wth[WT_TOTAL];

// ---------------------------------------------------------------------------
// Helpers
// ---------------------------------------------------------------------------
__device__ __forceinline__ float gelu_exact(float v) {
    return 0.5f * v * (1.0f + erff(v * 0.7071067811865476f));
}

// pair permutation within a 32-half block: pair q (0..15) -> 4*(q&3) + (q>>2)
__device__ __forceinline__ int permpair(int q) { return 4 * (q & 3) + (q >> 2); }
// permuted half index for single half c
__device__ __forceinline__ int permhs(int c) {
    int q = (c & 31) >> 1;
    return (c & ~31) + permpair(q) * 2 + (c & 1);
}

__device__ __forceinline__ uint32_t smem_u32(const void* p) {
    uint32_t a;
    asm("{ .reg .u64 t; cvta.to.shared.u64 t, %1; cvt.u32.u64 %0, t; }" : "=r"(a) : "l"(p));
    return a;
}
__device__ __forceinline__ void cp16(uint32_t s, const void* g) {
    asm volatile("cp.async.cg.shared.global [%0], [%1], 16;" :: "r"(s), "l"(g) : "memory");
}

#define MMA16(d, a0,a1,a2,a3, b0,b1) \
    asm volatile("mma.sync.aligned.m16n8k16.row.col.f32.f16.f16.f32 " \
        "{%0,%1,%2,%3},{%4,%5,%6,%7},{%8,%9},{%0,%1,%2,%3};" \
        : "+f"((d)[0]), "+f"((d)[1]), "+f"((d)[2]), "+f"((d)[3]) \
        : "r"(a0), "r"(a1), "r"(a2), "r"(a3), "r"(b0), "r"(b1))

// ---------------------------------------------------------------------------
// fp16 GEMM via mma.sync m16n8k16: C[M,N] = A[M,K] @ Bt[N,K]^T
// A, Bt: fp16, pair-permuted within each 32-half k-block, 16B-aligned rows.
// Epilogue: +bias(+z) +bias2 +resid(fp32); optional gelu.
// outHalf: C is __half*, written pair-permuted (feeds next GEMM's A).
// else C is float* plain. Cr (optional): extra fp16-permuted copy.
// ---------------------------------------------------------------------------
__global__ void __launch_bounds__(NTH, 2)
gemm_h(const __half* __restrict__ A, int lda, int az,
       const __half* __restrict__ Bt, int K, int bz,
       void* __restrict__ Cv, int ldc, int cz,
       __half* __restrict__ Cr,
       const float* __restrict__ bias, int biasz,
       const float* __restrict__ bias2,
       const float* __restrict__ resid, int ldres,
       int dogelu, int outHalf)
{
    extern __shared__ char smem[];
    const uint32_t sb = smem_u32(smem);

    A  += (size_t)blockIdx.z * az;
    Bt += (size_t)blockIdx.z * bz;
    if (bias) bias += (size_t)blockIdx.z * biasz;

    const int tid = threadIdx.x;
    const int wid = tid >> 5, lane = tid & 31;
    const int g = lane >> 2, tg = lane & 3;
    const int wm = wid & 3, wn = wid >> 2;        // 4x2 warp grid
    const int tile_m = blockIdx.y * BM;
    const int tile_n = blockIdx.x * BN;
    const int ktiles = K / BK;

    float acc[2][4][4];
    #pragma unroll
    for (int i = 0; i < 2; i++)
        #pragma unroll
        for (int j = 0; j < 4; j++)
            #pragma unroll
            for (int r = 0; r < 4; r++) acc[i][j][r] = 0.f;

    auto load_stage = [&](int buf, int k0) {
        // A: 512 x 16B chunks, 2 per thread
        #pragma unroll
        for (int i = 0; i < 2; i++) {
            int c = tid + i * NTH;
            int r = c >> 2, q = c & 3;
            cp16(sb + buf * STAGE_BYTES + r * 64 + q * 16,
                 A + (size_t)(tile_m + r) * lda + k0 + q * 8);
        }
        // B: 256 x 16B chunks, 1 per thread
        {
            int r = tid >> 2, q = tid & 3;
            cp16(sb + buf * STAGE_BYTES + A_TILE_BYTES + r * 64 + q * 16,
                 Bt + (size_t)(tile_n + r) * K + k0 + q * 8);
        }
    };

    load_stage(0, 0);
    asm volatile("cp.async.commit_group;" ::: "memory");
    load_stage(1, BK);
    asm volatile("cp.async.commit_group;" ::: "memory");

    for (int kt = 0; kt < ktiles; kt++) {
        asm volatile("cp.async.wait_group 1;" ::: "memory");
        __syncthreads();

        const char* as = smem + (kt % NSTAGE) * STAGE_BYTES;
        const char* bs = as + A_TILE_BYTES;

        // 8 LDS.128 per thread-free: 4 A + 4 B fragments cover both k-steps
        uint4 Ar[2][2], Br[4];
        #pragma unroll
        for (int mi = 0; mi < 2; mi++) {
            int r0 = wm * 32 + mi * 16 + g;
            Ar[mi][0] = *(const uint4*)(as + r0 * 64 + tg * 16);
            Ar[mi][1] = *(const uint4*)(as + (r0 + 8) * 64 + tg * 16);
        }
        #pragma unroll
        for (int ni = 0; ni < 4; ni++) {
            int r = wn * 32 + ni * 8 + g;
            Br[ni] = *(const uint4*)(bs + r * 64 + tg * 16);
        }

        // prefetch stage kt+2 — the 16 MMAs below cover its latency
        const int pf = kt + 2;
        if (pf < ktiles) load_stage(pf % NSTAGE, pf * BK);
        asm volatile("cp.async.commit_group;" ::: "memory");

        // k-step 0 uses .x/.y; k-step 1 uses .z/.w
        #pragma unroll
        for (int ni = 0; ni < 4; ni++)
            #pragma unroll
            for (int mi = 0; mi < 2; mi++) {
                MMA16(acc[mi][ni],
                      Ar[mi][0].x, Ar[mi][1].x, Ar[mi][0].y, Ar[mi][1].y,
                      Br[ni].x, Br[ni].y);
                MMA16(acc[mi][ni],
                      Ar[mi][0].z, Ar[mi][1].z, Ar[mi][0].w, Ar[mi][1].w,
                      Br[ni].z, Br[ni].w);
            }
    }

    // ---- epilogue ----
    #pragma unroll
    for (int mi = 0; mi < 2; mi++) {
        const int rbase = tile_m + wm * 32 + mi * 16 + g;
        #pragma unroll
        for (int rr = 0; rr < 2; rr++) {
            const int row = rbase + rr * 8;
            const float* resrow = resid ? resid + (size_t)row * ldres : nullptr;
            float*  crowf = outHalf ? nullptr
                          : (float*)Cv + (size_t)blockIdx.z * cz + (size_t)row * ldc;
            __half* crowh = outHalf
                          ? (__half*)Cv + (size_t)blockIdx.z * cz + (size_t)row * ldc
                          : nullptr;
            __half* crrow = Cr ? Cr + (size_t)row * ldc : nullptr;
            #pragma unroll
            for (int ni = 0; ni < 4; ni++) {
                const int c = tile_n + wn * 32 + ni * 8 + tg * 2;
                float v0 = acc[mi][ni][rr * 2 + 0];
                float v1 = acc[mi][ni][rr * 2 + 1];
                if (bias)   { v0 += bias[c];   v1 += bias[c + 1]; }
                if (bias2)  { v0 += bias2[c];  v1 += bias2[c + 1]; }
                if (resrow) { v0 += resrow[c]; v1 += resrow[c + 1]; }
                if (dogelu) { v0 = gelu_exact(v0); v1 = gelu_exact(v1); }
                // c is even: the pair (c, c+1) lands at one permuted half2
                int ph = (c & ~31) + permpair((c & 31) >> 1) * 2;
                if (outHalf) {
                    *(__half2*)(crowh + ph) = __floats2half2_rn(v0, v1);
                } else {
                    *(float2*)(crowf + c) = make_float2(v0, v1);
                }
                if (crrow)
                    *(__half2*)(crrow + ph) = __floats2half2_rn(v0, v1);
            }
        }
    }
}

// ---------------------------------------------------------------------------
// x prepass: fp16 convert + pair-permute (one 32-half block per thread)
// ---------------------------------------------------------------------------
__global__ void __launch_bounds__(256)
permute_x(const float* __restrict__ x, __half* __restrict__ xh)
{
    size_t idx = (size_t)blockIdx.x * 256 + threadIdx.x;
    const float4* src = (const float4*)(x + idx * 32);
    __half2* dst = (__half2*)(xh + idx * 32);
    float v[32];
    #pragma unroll
    for (int i = 0; i < 8; i++) {
        float4 u = src[i];
        v[i * 4 + 0] = u.x; v[i * 4 + 1] = u.y;
        v[i * 4 + 2] = u.z; v[i * 4 + 3] = u.w;
    }
    #pragma unroll
    for (int q = 0; q < 16; q++)
        dst[permpair(q)] = __floats2half2_rn(v[2 * q], v[2 * q + 1]);
}

// ---------------------------------------------------------------------------
// Weight prepass: ONE launch. W[K,N] -> Wt[N,K] fp16, pair-permuted.
// ---------------------------------------------------------------------------
#define NWT 13
struct TTable {
    const float* W[NWT];
    __half*      Wt[NWT];
    int K[NWT], N[NWT], t0[NWT];
};

__global__ void __launch_bounds__(256)
transpose_all(TTable tab)
{
    __shared__ float ts[32][33];
    int bid = blockIdx.x;
    int e = 0;
    #pragma unroll
    for (int i = 1; i < NWT; i++)
        if (bid >= tab.t0[i]) e = i;
    int t  = bid - tab.t0[e];
    int nx = tab.N[e] >> 5;
    int n0 = (t % nx) << 5, k0 = (t / nx) << 5;
    const float* W = tab.W[e];
    __half* Wt = tab.Wt[e];
    int K = tab.K[e], N = tab.N[e];
    int tx = threadIdx.x & 31, ty = threadIdx.x >> 5;   // 32 x 8
    #pragma unroll
    for (int j = 0; j < 32; j += 8)
        ts[ty + j][tx] = W[(size_t)(k0 + ty + j) * N + n0 + tx];
    __syncthreads();
    int pk = permpair(tx >> 1) * 2 + (tx & 1);          // permuted pos of k=tx
    #pragma unroll
    for (int j = 0; j < 32; j += 8)
        Wt[(size_t)(n0 + ty + j) * K + k0 + pk] = __float2half_rn(ts[tx][ty + j]);
}

// ---------------------------------------------------------------------------
// LayerNorms (fp32 in, fp16 pair-permuted out: they feed GEMM A operands)
// ---------------------------------------------------------------------------
__device__ __forceinline__ void blockreduce2(float& s, float& q, float* red, int nwarps) {
    #pragma unroll
    for (int o = 16; o > 0; o >>= 1) {
        s += __shfl_xor_sync(0xFFFFFFFFu, s, o);
        q += __shfl_xor_sync(0xFFFFFFFFu, q, o);
    }
    int warp = threadIdx.x >> 5, lane = threadIdx.x & 31;
    if (lane == 0) { red[warp] = s; red[warp + 8] = q; }
    __syncthreads();
    s = 0.f; q = 0.f;
    for (int w = 0; w < nwarps; w++) { s += red[w]; q += red[w + 8]; }
}

__global__ void ln512(const float* __restrict__ x, __half* __restrict__ y,
                      const float* __restrict__ gam, const float* __restrict__ bet)
{
    __shared__ float red[16];
    int row = blockIdx.x;
    int t = threadIdx.x;                          // 128 threads, 4 cols each
    const float4* xr = (const float4*)(x + (size_t)row * DMODEL);
    float4 a = xr[t];
    float s = a.x + a.y + a.z + a.w;
    float q = a.x * a.x + a.y * a.y + a.z * a.z + a.w * a.w;
    blockreduce2(s, q, red, 4);
    float m  = s * (1.f / DMODEL);
    float va = q * (1.f / DMODEL) - m * m;
    float rs = rsqrtf(va + 1e-5f);
    float4 gg = ((const float4*)gam)[t];
    float4 bb = ((const float4*)bet)[t];
    float o0 = (a.x - m) * rs * gg.x + bb.x;
    float o1 = (a.y - m) * rs * gg.y + bb.y;
    float o2 = (a.z - m) * rs * gg.z + bb.z;
    float o3 = (a.w - m) * rs * gg.w + bb.w;
    __half* yr = y + (size_t)row * DMODEL;
    int c = 4 * t;                                // even, two pairs q0, q0+1
    int blockbase = c & ~31;
    int q0 = (c & 31) >> 1;
    *(__half2*)(yr + blockbase + permpair(q0) * 2)     = __floats2half2_rn(o0, o1);
    *(__half2*)(yr + blockbase + permpair(q0 + 1) * 2) = __floats2half2_rn(o2, o3);
}

__global__ void head_gelu_ln(const float* __restrict__ z, __half* __restrict__ y,
                             const float* __restrict__ gam, const float* __restrict__ bet)
{
    __shared__ float red[16];
    int b = blockIdx.x, h = blockIdx.y;
    int c = threadIdx.x;                           // 256 threads
    int base = b * (NHEAD * HDIM) + h * HDIM;
    float v = gelu_exact(z[base + c]);
    float s = v, q = v * v;
    blockreduce2(s, q, red, 8);
    float m  = s * (1.f / HDIM);
    float va = q * (1.f / HDIM) - m * m;
    float rs = rsqrtf(va + 1e-5f);
    float o = (v - m) * rs * gam[h * HDIM + c] + bet[h * HDIM + c];
    y[base + permhs(c)] = __float2half_rn(o);
}

// ---------------------------------------------------------------------------
// Launch
// ---------------------------------------------------------------------------
extern "C" void kernel_launch(void* const* d_in, const int* in_sizes, int n_in,
                              void* d_out, int out_size)
{
    (void)in_sizes; (void)n_in; (void)out_size;
    const float* x       = (const float*)d_in[0];
    const float* w_in    = (const float*)d_in[1];
    const float* b_in    = (const float*)d_in[2];
    const float* pos     = (const float*)d_in[3];
    const float* ln1_g   = (const float*)d_in[4];
    const float* ln1_b   = (const float*)d_in[5];
    const float* wv_sa   = (const float*)d_in[6];
    const float* bv_sa   = (const float*)d_in[7];
    const float* wo_sa   = (const float*)d_in[8];
    const float* bo_sa   = (const float*)d_in[9];
    const float* wv_ca   = (const float*)d_in[12];
    const float* bv_ca   = (const float*)d_in[13];
    const float* wo_ca   = (const float*)d_in[14];
    const float* bo_ca   = (const float*)d_in[15];
    const float* ln3_g   = (const float*)d_in[16];
    const float* ln3_b   = (const float*)d_in[17];
    const float* w_ff1   = (const float*)d_in[18];
    const float* b_ff1   = (const float*)d_in[19];
    const float* w_ff2   = (const float*)d_in[20];
    const float* b_ff2   = (const float*)d_in[21];
    const float* lnout_g = (const float*)d_in[22];
    const float* lnout_b = (const float*)d_in[23];
    const float* wh1     = (const float*)d_in[24];
    const float* bh1     = (const float*)d_in[25];
    const float* lnh_g   = (const float*)d_in[26];
    const float* lnh_b   = (const float*)d_in[27];
    const float* wh2     = (const float*)d_in[28];
    const float* bh2     = (const float*)d_in[29];
    float* out = (float*)d_out;

    __half *xh, *h0rh, *lnbh, *th, *ffh, *z2h, *wth;
    float *h0, *h, *z;
    cudaGetSymbolAddress((void**)&xh,   g_xh);
    cudaGetSymbolAddress((void**)&h0,   g_h0);
    cudaGetSymbolAddress((void**)&h0rh, g_h0rh);
    cudaGetSymbolAddress((void**)&h,    g_h);
    cudaGetSymbolAddress((void**)&lnbh, g_lnbh);
    cudaGetSymbolAddress((void**)&th,   g_th);
    cudaGetSymbolAddress((void**)&ffh,  g_ffh);
    cudaGetSymbolAddress((void**)&z,    g_z);
    cudaGetSymbolAddress((void**)&z2h,  g_z2h);
    cudaGetSymbolAddress((void**)&wth,  g_wth);

    cudaFuncSetAttribute(gemm_h,
                         cudaFuncAttributeMaxDynamicSharedMemorySize, SMEM_BYTES);

    // ---- prepasses ----
    permute_x<<<(BATCH * DIN / 32) / 256, 256>>>(x, xh);
    {
        TTable tab;
        int idx = 0, acc = 0;
        auto add = [&](const float* W, __half* Wt, int K, int N) {
            tab.W[idx] = W; tab.Wt[idx] = Wt; tab.K[idx] = K; tab.N[idx] = N;
            tab.t0[idx] = acc; acc += (K / 32) * (N / 32); idx++;
        };
        add(w_in,  wth + OFF_WIN,  DIN,    DMODEL);
        add(wv_sa, wth + OFF_WVSA, DMODEL, DMODEL);
        add(wo_sa, wth + OFF_WOSA, DMODEL, DMODEL);
        add(wv_ca, wth + OFF_WVCA, DMODEL, DMODEL);
        add(wo_ca, wth + OFF_WOCA, DMODEL, DMODEL);
        add(w_ff1, wth + OFF_FF1,  DMODEL, DFF);
        add(w_ff2, wth + OFF_FF2,  DFF,    DMODEL);
        for (int hh = 0; hh < NHEAD; hh++)
            add(wh1 + (size_t)hh * DMODEL * HDIM,
                wth + OFF_WH1 + (size_t)hh * HDIM * DMODEL, DMODEL, HDIM);
        for (int hh = 0; hh < NHEAD; hh++)
            add(wh2 + (size_t)hh * HDIM * OUTD,
                wth + OFF_WH2 + (size_t)hh * OUTD * HDIM, HDIM, OUTD);
        transpose_all<<<acc, 256>>>(tab);
    }

    auto G = [&](const __half* A, int lda, int az,
                 const __half* Bt, int K, int bz,
                 void* C, int ldc, int cz, __half* Cr,
                 const float* b1, int b1z, const float* b2,
                 const float* res, int ldres,
                 int dg, int oh, int M, int N, int nz) {
        dim3 grid(N / BN, M / BM, nz);
        gemm_h<<<grid, NTH, SMEM_BYTES>>>(A, lda, az, Bt, K, bz,
            C, ldc, cz, Cr, b1, b1z, b2, res, ldres, dg, oh);
    };

    // 1. h0 = x @ w_in + b_in + pos (fp32); h0rh = fp16 permuted copy
    G(xh, DIN, 0, wth + OFF_WIN, DIN, 0, h0, DMODEL, 0, h0rh,
      b_in, 0, pos, nullptr, 0, 0, 0, BATCH, DMODEL, 1);
    // 2. lnbh = LN(h0; ln1)
    ln512<<<BATCH, 128>>>(h0, lnbh, ln1_g, ln1_b);
    // 3. th = lnbh @ wv_sa + bv_sa  (fp16 out)
    G(lnbh, DMODEL, 0, wth + OFF_WVSA, DMODEL, 0, th, DMODEL, 0, nullptr,
      bv_sa, 0, nullptr, nullptr, 0, 0, 1, BATCH, DMODEL, 1);
    // 4. h = h0 + th @ wo_sa + bo_sa  (fp32)
    G(th, DMODEL, 0, wth + OFF_WOSA, DMODEL, 0, h, DMODEL, 0, nullptr,
      bo_sa, 0, nullptr, h0, DMODEL, 0, 0, BATCH, DMODEL, 1);
    // 5. th = h0rh @ wv_ca + bv_ca  (fp16 out)
    G(h0rh, DMODEL, 0, wth + OFF_WVCA, DMODEL, 0, th, DMODEL, 0, nullptr,
      bv_ca, 0, nullptr, nullptr, 0, 0, 1, BATCH, DMODEL, 1);
    // 6. h = h + th @ wo_ca + bo_ca  (in-place residual: same elem, same thread)
    G(th, DMODEL, 0, wth + OFF_WOCA, DMODEL, 0, h, DMODEL, 0, nullptr,
      bo_ca, 0, nullptr, h, DMODEL, 0, 0, BATCH, DMODEL, 1);
    // 7. lnbh = LN(h; ln3)
    ln512<<<BATCH, 128>>>(h, lnbh, ln3_g, ln3_b);
    // 8. ffh = gelu(lnbh @ w_ff1 + b_ff1)  (fp16 out)
    G(lnbh, DMODEL, 0, wth + OFF_FF1, DMODEL, 0, ffh, DFF, 0, nullptr,
      b_ff1, 0, nullptr, nullptr, 0, 1, 1, BATCH, DFF, 1);
    // 9. h = h + ffh @ w_ff2 + b_ff2  (fp32)
    G(ffh, DFF, 0, wth + OFF_FF2, DFF, 0, h, DMODEL, 0, nullptr,
      b_ff2, 0, nullptr, h, DMODEL, 0, 0, BATCH, DMODEL, 1);
    // 10. lnbh = LN(h; lnout)
    ln512<<<BATCH, 128>>>(h, lnbh, lnout_g, lnout_b);
    // 11. z[:, hh] = lnbh @ wh1[hh] + bh1[hh]  (fp32, batched over heads)
    G(lnbh, DMODEL, 0, wth + OFF_WH1, DMODEL, HDIM * DMODEL,
      z, NHEAD * HDIM, HDIM, nullptr,
      bh1, HDIM, nullptr, nullptr, 0, 0, 0, BATCH, HDIM, NHEAD);
    // 12. z2h = LN(gelu(z)) per head  (fp16 out)
    head_gelu_ln<<<dim3(BATCH, NHEAD), 256>>>(z, z2h, lnh_g, lnh_b);
    // 13. out[:, hh, :] = z2h[:, hh] @ wh2[hh] + bh2[hh]  (fp32, batched)
    G(z2h, NHEAD * HDIM, HDIM, wth + OFF_WH2, HDIM, OUTD * HDIM,
      out, NHEAD * OUTD, OUTD, nullptr,
      bh2, OUTD, nullptr, nullptr, 0, 0, 0, BATCH, OUTD, NHEAD);
}